// round 2
// baseline (speedup 1.0000x reference)
#include <cuda_runtime.h>
#include <cuda_bf16.h>
#include <cstdint>

// Problem constants: N = 1048576 rows, D = 64 f32 per row (256 B).
constexpr int N_ELEMS = 1 << 20;
constexpr int TILE    = 256;                 // rows per tile / per scatter block
constexpr int NTILES  = N_ELEMS / TILE;      // 4096

// Scratch (device-global; no allocation allowed)
__device__ int g_tileCounts[NTILES];
__device__ int g_tileOffsets[NTILES];

// ---------------------------------------------------------------------------
// Kernel 1: per-tile count of (partitions == 0). 4096 blocks x 64 threads,
// each thread reads int4 (4 elems) -> 256 elems per tile.
// ---------------------------------------------------------------------------
__global__ void count_k(const int* __restrict__ part) {
    int tile = blockIdx.x;
    int4 p = *reinterpret_cast<const int4*>(part + tile * TILE + threadIdx.x * 4);
    int c = (p.x == 0) + (p.y == 0) + (p.z == 0) + (p.w == 0);

    #pragma unroll
    for (int o = 16; o; o >>= 1) c += __shfl_down_sync(0xffffffffu, c, o);

    __shared__ int s;
    if (threadIdx.x == 0) s = 0;
    __syncthreads();
    if ((threadIdx.x & 31) == 0) atomicAdd(&s, c);
    __syncthreads();
    if (threadIdx.x == 0) g_tileCounts[tile] = s;
}

// ---------------------------------------------------------------------------
// Kernel 2: exclusive scan of 4096 tile counts. One block, 1024 threads,
// 4 consecutive tiles per thread.
// ---------------------------------------------------------------------------
__global__ void scan_k() {
    int t = threadIdx.x;                       // 0..1023
    int4 v = *reinterpret_cast<const int4*>(g_tileCounts + t * 4);
    int sum = v.x + v.y + v.z + v.w;

    int lane = t & 31, w = t >> 5;             // 32 warps
    int s = sum;
    #pragma unroll
    for (int o = 1; o < 32; o <<= 1) {
        int n = __shfl_up_sync(0xffffffffu, s, o);
        if (lane >= o) s += n;
    }
    __shared__ int wsum[32];
    if (lane == 31) wsum[w] = s;
    __syncthreads();
    if (w == 0) {
        int x = wsum[lane];
        #pragma unroll
        for (int o = 1; o < 32; o <<= 1) {
            int n = __shfl_up_sync(0xffffffffu, x, o);
            if (lane >= o) x += n;
        }
        wsum[lane] = x;
    }
    __syncthreads();

    int excl = s - sum + (w > 0 ? wsum[w - 1] : 0);
    int4 o;
    o.x = excl;
    o.y = excl + v.x;
    o.z = excl + v.x + v.y;
    o.w = excl + v.x + v.y + v.z;
    *reinterpret_cast<int4*>(g_tileOffsets + t * 4) = o;
}

// ---------------------------------------------------------------------------
// Kernel 3 (fused): per-tile dest computation + row scatter.
// Block = 256 threads handles one tile of 256 rows:
//   phase A: ballot-scan of partition predicates -> global zero-rank -> dest
//   phase B: copy 256 rows x 256 B; reads coalesced & streaming, each row's
//            write is one contiguous 256 B chunk at a random row offset.
// ---------------------------------------------------------------------------
__global__ void __launch_bounds__(256) scatter_fused_k(
        const int*   __restrict__ part,
        const int*   __restrict__ idx0,
        const int*   __restrict__ idx1,
        const float4* __restrict__ in,
        float4*       __restrict__ out) {
    int tile = blockIdx.x;
    int t    = threadIdx.x;
    int gi   = tile * TILE + t;

    // --- phase A: destination rows ---
    int b = (part[gi] == 0);
    int lane = t & 31, w = t >> 5;
    unsigned bal = __ballot_sync(0xffffffffu, b);
    int within = __popc(bal & ((1u << lane) - 1u));
    int wtotal = __popc(bal);

    __shared__ int wsum[8];
    __shared__ int sdest[TILE];
    if (lane == 0) wsum[w] = wtotal;
    __syncthreads();

    int woff = 0;
    #pragma unroll
    for (int i = 0; i < 8; i++) woff += (i < w) ? wsum[i] : 0;

    int zb = g_tileOffsets[tile] + woff + within;   // global zeros before gi
    int dest = b ? __ldg(idx0 + zb) : __ldg(idx1 + (gi - zb));
    sdest[t] = dest;
    __syncthreads();

    // --- phase B: 256 rows * 16 float4 slots = 4096 slots, 16 per thread ---
    const float4* src = in + (size_t)tile * TILE * 16;
    #pragma unroll
    for (int k = 0; k < 16; k++) {
        int s   = t + k * 256;
        int row = s >> 4;
        int ln  = s & 15;
        float4 v = __ldcs(src + s);                 // read-once, evict-first
        out[(size_t)sdest[row] * 16 + ln] = v;
    }
}

// ---------------------------------------------------------------------------
extern "C" void kernel_launch(void* const* d_in, const int* in_sizes, int n_in,
                              void* d_out, int out_size) {
    const float* data = (const float*)d_in[0];
    const int*   part = (const int*)d_in[1];
    const int*   idx0 = (const int*)d_in[2];
    const int*   idx1 = (const int*)d_in[3];
    float* out = (float*)d_out;

    count_k<<<NTILES, 64>>>(part);
    scan_k<<<1, 1024>>>();
    scatter_fused_k<<<NTILES, 256>>>(part, idx0, idx1,
                                     (const float4*)data, (float4*)out);
}

// round 3
// speedup vs baseline: 1.1053x; 1.1053x over previous
#include <cuda_runtime.h>
#include <cuda_bf16.h>
#include <cstdint>

// N = 1048576 rows, D = 64 f32 per row (256 B/row).
constexpr int N_ELEMS = 1 << 20;
constexpr int TILE    = 256;                 // rows per scatter block
constexpr int NTILES  = N_ELEMS / TILE;      // 4096

__device__ __align__(16) int g_tileCounts[NTILES];
__device__ __align__(16) int g_tileOffsets[NTILES];

// ---------------------------------------------------------------------------
// Kernel 1: per-tile zero counts. 256 blocks x 256 threads.
// Each thread reads 16 consecutive ints (4 x int4 = 64 B); a tile (256 elems)
// is covered by 16 consecutive threads -> width-16 shfl reduction.
// ---------------------------------------------------------------------------
__global__ void __launch_bounds__(256) count_k(const int* __restrict__ part) {
    int t = threadIdx.x;
    const int4* p4 = reinterpret_cast<const int4*>(part) + blockIdx.x * 1024 + t * 4;

    int c = 0;
    #pragma unroll
    for (int k = 0; k < 4; k++) {
        int4 p = p4[k];
        c += (p.x == 0) + (p.y == 0) + (p.z == 0) + (p.w == 0);
    }

    // reduce across 16 lanes (one tile)
    #pragma unroll
    for (int o = 8; o; o >>= 1) c += __shfl_down_sync(0xffffffffu, c, o, 16);

    if ((t & 15) == 0)
        g_tileCounts[blockIdx.x * 16 + (t >> 4)] = c;
}

// ---------------------------------------------------------------------------
// Kernel 2: exclusive scan of 4096 tile counts (1 block, 1024 threads, int4).
// ---------------------------------------------------------------------------
__global__ void scan_k() {
    int t = threadIdx.x;
    int4 v = *reinterpret_cast<const int4*>(g_tileCounts + t * 4);
    int sum = v.x + v.y + v.z + v.w;

    int lane = t & 31, w = t >> 5;
    int s = sum;
    #pragma unroll
    for (int o = 1; o < 32; o <<= 1) {
        int n = __shfl_up_sync(0xffffffffu, s, o);
        if (lane >= o) s += n;
    }
    __shared__ int wsum[32];
    if (lane == 31) wsum[w] = s;
    __syncthreads();
    if (w == 0) {
        int x = wsum[lane];
        #pragma unroll
        for (int o = 1; o < 32; o <<= 1) {
            int n = __shfl_up_sync(0xffffffffu, x, o);
            if (lane >= o) x += n;
        }
        wsum[lane] = x;
    }
    __syncthreads();

    int excl = s - sum + (w > 0 ? wsum[w - 1] : 0);
    int4 o;
    o.x = excl;
    o.y = excl + v.x;
    o.z = excl + v.x + v.y;
    o.w = excl + v.x + v.y + v.z;
    *reinterpret_cast<int4*>(g_tileOffsets + t * 4) = o;
}

// ---------------------------------------------------------------------------
// Kernel 3 (fused): dest computation + row scatter, with phase-A latency
// hidden behind the first 8 row-chunk loads.
// ---------------------------------------------------------------------------
__global__ void __launch_bounds__(256) scatter_fused_k(
        const int*    __restrict__ part,
        const int*    __restrict__ idx0,
        const int*    __restrict__ idx1,
        const float4* __restrict__ in,
        float4*       __restrict__ out) {
    int tile = blockIdx.x;
    int t    = threadIdx.x;
    int gi   = tile * TILE + t;
    const float4* src = in + (size_t)tile * TILE * 16;

    // --- prefetch first half of the tile's data (32 regs) ---
    float4 v[8];
    #pragma unroll
    for (int k = 0; k < 8; k++) v[k] = src[t + k * 256];

    // --- phase A: destination rows (overlaps with the loads above) ---
    int b = (part[gi] == 0);
    int lane = t & 31, w = t >> 5;
    unsigned bal = __ballot_sync(0xffffffffu, b);
    int within = __popc(bal & ((1u << lane) - 1u));
    int wtotal = __popc(bal);

    __shared__ int wsum[8];
    __shared__ int sdest[TILE];
    if (lane == 0) wsum[w] = wtotal;
    __syncthreads();

    int woff = 0;
    #pragma unroll
    for (int i = 0; i < 8; i++) woff += (i < w) ? wsum[i] : 0;

    int zb = g_tileOffsets[tile] + woff + within;
    sdest[t] = b ? __ldg(idx0 + zb) : __ldg(idx1 + (gi - zb));
    __syncthreads();

    // --- store prefetched half ---
    #pragma unroll
    for (int k = 0; k < 8; k++) {
        int s   = t + k * 256;
        int row = s >> 4;
        int ln  = s & 15;
        out[(size_t)sdest[row] * 16 + ln] = v[k];
    }
    // --- stream second half ---
    #pragma unroll
    for (int k = 8; k < 16; k++) {
        int s   = t + k * 256;
        int row = s >> 4;
        int ln  = s & 15;
        out[(size_t)sdest[row] * 16 + ln] = src[s];
    }
}

// ---------------------------------------------------------------------------
extern "C" void kernel_launch(void* const* d_in, const int* in_sizes, int n_in,
                              void* d_out, int out_size) {
    const float* data = (const float*)d_in[0];
    const int*   part = (const int*)d_in[1];
    const int*   idx0 = (const int*)d_in[2];
    const int*   idx1 = (const int*)d_in[3];
    float* out = (float*)d_out;

    count_k<<<256, 256>>>(part);
    scan_k<<<1, 1024>>>();
    scatter_fused_k<<<NTILES, 256>>>(part, idx0, idx1,
                                     (const float4*)data, (float4*)out);
}

// round 4
// speedup vs baseline: 1.1365x; 1.0283x over previous
#include <cuda_runtime.h>
#include <cuda_bf16.h>
#include <cstdint>

// N = 1048576 rows, D = 64 f32 per row (256 B/row).
constexpr int N_ELEMS = 1 << 20;
constexpr int TILE    = 256;                 // rows per scatter block
constexpr int NTILES  = N_ELEMS / TILE;      // 4096

__device__ __align__(16) int g_tileCounts[NTILES];

// ---------------------------------------------------------------------------
// Kernel 1: per-tile zero counts. 1024 blocks x 256 threads, int4 per thread.
// Block covers 1024 elems = 4 tiles; each warp covers half a tile.
// ---------------------------------------------------------------------------
__global__ void __launch_bounds__(256) count_k(const int* __restrict__ part) {
    int t = threadIdx.x;
    int4 p = reinterpret_cast<const int4*>(part)[blockIdx.x * 256 + t];
    int c = (p.x == 0) + (p.y == 0) + (p.z == 0) + (p.w == 0);

    #pragma unroll
    for (int o = 16; o; o >>= 1) c += __shfl_down_sync(0xffffffffu, c, o);

    __shared__ int s[4];                      // one per tile in this block
    if (t < 4) s[t] = 0;
    __syncthreads();
    int w = t >> 5;                            // warp 0..7; tile = w>>1
    if ((t & 31) == 0) atomicAdd(&s[w >> 1], c);
    __syncthreads();
    if (t < 4) g_tileCounts[blockIdx.x * 4 + t] = s[t];
}

// ---------------------------------------------------------------------------
// Kernel 2 (fused): tile-offset reduce (over L2-hot g_tileCounts) + dest
// computation + row scatter. Offset/ballot latency hidden behind an
// 8-chunk register prefetch of the tile's data.
// ---------------------------------------------------------------------------
__global__ void __launch_bounds__(256) scatter_fused_k(
        const int*    __restrict__ part,
        const int*    __restrict__ idx0,
        const int*    __restrict__ idx1,
        const float4* __restrict__ in,
        float4*       __restrict__ out) {
    int tile = blockIdx.x;
    int t    = threadIdx.x;
    int gi   = tile * TILE + t;
    const float4* src = in + (size_t)tile * TILE * 16;

    // --- prefetch first half of the tile's data (32 regs) ---
    float4 v[8];
    #pragma unroll
    for (int k = 0; k < 8; k++) v[k] = src[t + k * 256];

    // --- partition predicate + warp ballot scan ---
    int b = (part[gi] == 0);
    int lane = t & 31, w = t >> 5;
    unsigned bal = __ballot_sync(0xffffffffu, b);
    int within = __popc(bal & ((1u << lane) - 1u));
    int wtotal = __popc(bal);

    // --- tile offset: sum of g_tileCounts[0..tile) (L2-resident, 16 KB) ---
    int acc = 0;
    for (int i = t; i < tile; i += 256) acc += __ldg(g_tileCounts + i);
    #pragma unroll
    for (int o = 16; o; o >>= 1) acc += __shfl_down_sync(0xffffffffu, acc, o);

    __shared__ int rsum[8];   // per-warp partial tile-offset sums
    __shared__ int wsum[8];   // per-warp zero counts (ballot)
    __shared__ int sdest[TILE];
    if (lane == 0) { rsum[w] = acc; wsum[w] = wtotal; }
    __syncthreads();

    int tileOff = 0, woff = 0;
    #pragma unroll
    for (int i = 0; i < 8; i++) {
        tileOff += rsum[i];
        woff    += (i < w) ? wsum[i] : 0;
    }

    int zb = tileOff + woff + within;            // global zeros before gi
    sdest[t] = b ? __ldg(idx0 + zb) : __ldg(idx1 + (gi - zb));
    __syncthreads();

    // --- store prefetched half ---
    #pragma unroll
    for (int k = 0; k < 8; k++) {
        int s   = t + k * 256;
        int row = s >> 4;
        int ln  = s & 15;
        out[(size_t)sdest[row] * 16 + ln] = v[k];
    }
    // --- stream second half ---
    #pragma unroll
    for (int k = 8; k < 16; k++) {
        int s   = t + k * 256;
        int row = s >> 4;
        int ln  = s & 15;
        out[(size_t)sdest[row] * 16 + ln] = src[s];
    }
}

// ---------------------------------------------------------------------------
extern "C" void kernel_launch(void* const* d_in, const int* in_sizes, int n_in,
                              void* d_out, int out_size) {
    const float* data = (const float*)d_in[0];
    const int*   part = (const int*)d_in[1];
    const int*   idx0 = (const int*)d_in[2];
    const int*   idx1 = (const int*)d_in[3];
    float* out = (float*)d_out;

    count_k<<<1024, 256>>>(part);
    scatter_fused_k<<<NTILES, 256>>>(part, idx0, idx1,
                                     (const float4*)data, (float4*)out);
}